// round 6
// baseline (speedup 1.0000x reference)
#include <cuda_runtime.h>
#include <cuda_bf16.h>
#include <math.h>
#include <stdint.h>

#define D_IN 1024
#define NHEAD 16
#define NHID 64
#define BATCH 2
#define SEQ 2048
#define MTOT (BATCH * SEQ)   /* 4096 */
#define NTOT (NHEAD * NHID)  /* 1024 */
#define BH (BATCH * NHEAD)   /* 32 */
#define DPAIRS (NHID / 2)    /* 32 */
#define SPAIRS (SEQ / 2)     /* 1024 */

// Scratch: bf16 hi/lo planes, k-pairs permuted [p0,p4,p1,p5,p2,p6,p3,p7] per 8-pair group.
// Q/K: (B,H,S, Dh-pairs). Q pre-scaled by 0.125. V stored transposed: (B,H,Dh, S-pairs).
__device__ uint32_t g_Qh[(size_t)BH * SEQ * DPAIRS];
__device__ uint32_t g_Ql[(size_t)BH * SEQ * DPAIRS];
__device__ uint32_t g_Kh[(size_t)BH * SEQ * DPAIRS];
__device__ uint32_t g_Kl[(size_t)BH * SEQ * DPAIRS];
__device__ uint32_t g_VTh[(size_t)BH * NHID * SPAIRS];
__device__ uint32_t g_VTl[(size_t)BH * NHID * SPAIRS];

// ---------------------------------------------------------------------------
// helpers
// ---------------------------------------------------------------------------
__device__ __forceinline__ int permpos(int p) { return p < 4 ? 2 * p : 2 * p - 7; }

// Split (a,b) into packed bf16 hi pair + lo pair (a in low half).
__device__ __forceinline__ void split_pair(float a, float b, uint32_t& h, uint32_t& l) {
    __nv_bfloat162 H = __floats2bfloat162_rn(a, b);
    float2 Hf = __bfloat1622float2(H);
    __nv_bfloat162 L = __floats2bfloat162_rn(a - Hf.x, b - Hf.y);
    h = *reinterpret_cast<uint32_t*>(&H);
    l = *reinterpret_cast<uint32_t*>(&L);
}

__device__ __forceinline__ void mma_bf16(float* d, const uint32_t* a, uint2 b) {
    asm volatile(
        "mma.sync.aligned.m16n8k16.row.col.f32.bf16.bf16.f32 "
        "{%0,%1,%2,%3}, {%4,%5,%6,%7}, {%8,%9}, {%0,%1,%2,%3};\n"
        : "+f"(d[0]), "+f"(d[1]), "+f"(d[2]), "+f"(d[3])
        : "r"(a[0]), "r"(a[1]), "r"(a[2]), "r"(a[3]), "r"(b.x), "r"(b.y));
}

__device__ __forceinline__ void cp_async16(uint32_t dst, const void* src) {
    asm volatile("cp.async.cg.shared.global [%0], [%1], 16;\n" :: "r"(dst), "l"(src));
}
__device__ __forceinline__ void cp_commit() {
    asm volatile("cp.async.commit_group;\n");
}
template <int N>
__device__ __forceinline__ void cp_wait() {
    asm volatile("cp.async.wait_group %0;\n" :: "n"(N));
}

// ---------------------------------------------------------------------------
// Fused QKV GEMM, bf16-split 3-term MMA. Block 128x128, ktile 32, 8 warps
// (warp 32m x 64n). Staging: LDG fp32 -> split -> STS (permuted pairs).
// Plane row stride 24 words (16 pairs + 8 pad; 24 = 8 mod 32 -> LDS.64 clean).
// ---------------------------------------------------------------------------
#define G_STRIDE 24
#define G_PLANE (128 * G_STRIDE)       /* 3072 words */
#define TS_LD 130
#define GEMM_SMEM_WORDS (128 * TS_LD)  /* 16640 > 4*G_PLANE=12288 */
#define GEMM_SMEM_BYTES (GEMM_SMEM_WORDS * 4)

__global__ __launch_bounds__(256) void qkv_gemm_bf16(
    const float* __restrict__ xq, const float* __restrict__ xk, const float* __restrict__ xv,
    const float* __restrict__ wq, const float* __restrict__ bq,
    const float* __restrict__ wk, const float* __restrict__ bk,
    const float* __restrict__ wv, const float* __restrict__ bv)
{
    extern __shared__ uint32_t smw[];
    uint32_t* Ah = smw;
    uint32_t* Al = smw + G_PLANE;
    uint32_t* Bh = smw + 2 * G_PLANE;
    uint32_t* Bl = smw + 3 * G_PLANE;

    const int z = blockIdx.z;
    const float* X    = (z == 0) ? xq : (z == 1) ? xk : xv;
    const float* W    = (z == 0) ? wq : (z == 1) ? wk : wv;
    const float* bias = (z == 0) ? bq : (z == 1) ? bk : bv;

    const int tid = threadIdx.x;
    const int bm = blockIdx.y * 128;
    const int bn = blockIdx.x * 128;
    const int warp = tid >> 5, lane = tid & 31;
    const int g = lane >> 2, t = lane & 3;
    const int wm = (warp >> 1) * 32;
    const int wn = (warp & 1) * 64;

    const int lrow = tid >> 1;
    const int khalf = (tid & 1) * 16;
    const float* Asrc = X + (size_t)(bm + lrow) * D_IN + khalf;
    const float* Bsrc = W + (size_t)(bn + lrow) * D_IN + khalf;

    float acc[2][8][4];
#pragma unroll
    for (int mt = 0; mt < 2; mt++)
#pragma unroll
        for (int j = 0; j < 8; j++)
#pragma unroll
            for (int c = 0; c < 4; c++) acc[mt][j][c] = 0.0f;

    float4 ra[4], rb[4];
#pragma unroll
    for (int ii = 0; ii < 4; ii++) {
        ra[ii] = *(const float4*)(Asrc + ii * 4);
        rb[ii] = *(const float4*)(Bsrc + ii * 4);
    }

    const int NKT = D_IN / 32;  // 32
    for (int kt = 0; kt < NKT; kt++) {
        __syncthreads();
        // STS staged regs (split + permute)
#pragma unroll
        for (int ii = 0; ii < 4; ii++) {
            const int ap0 = (khalf >> 1) + 2 * ii;
            const int w0 = (ap0 >> 3) * 8 + permpos(ap0 & 7);
            uint32_t h0, l0, h1, l1;
            split_pair(ra[ii].x, ra[ii].y, h0, l0);
            split_pair(ra[ii].z, ra[ii].w, h1, l1);
            Ah[lrow * G_STRIDE + w0] = h0; Ah[lrow * G_STRIDE + w0 + 2] = h1;
            Al[lrow * G_STRIDE + w0] = l0; Al[lrow * G_STRIDE + w0 + 2] = l1;
            split_pair(rb[ii].x, rb[ii].y, h0, l0);
            split_pair(rb[ii].z, rb[ii].w, h1, l1);
            Bh[lrow * G_STRIDE + w0] = h0; Bh[lrow * G_STRIDE + w0 + 2] = h1;
            Bl[lrow * G_STRIDE + w0] = l0; Bl[lrow * G_STRIDE + w0 + 2] = l1;
        }
        __syncthreads();
        if (kt < NKT - 1) {
            const float* a = Asrc + (kt + 1) * 32;
            const float* b = Bsrc + (kt + 1) * 32;
#pragma unroll
            for (int ii = 0; ii < 4; ii++) {
                ra[ii] = *(const float4*)(a + ii * 4);
                rb[ii] = *(const float4*)(b + ii * 4);
            }
        }
        // MMA: 2 k16 groups per ktile
#pragma unroll
        for (int ks = 0; ks < 2; ks++) {
            uint32_t afh[2][4], afl[2][4];
#pragma unroll
            for (int mt = 0; mt < 2; mt++) {
                const uint32_t* p = Ah + (wm + mt * 16 + g) * G_STRIDE + ks * 8 + 2 * t;
                uint2 x0 = *(const uint2*)p;
                uint2 x1 = *(const uint2*)(p + 8 * G_STRIDE);
                afh[mt][0] = x0.x; afh[mt][1] = x1.x; afh[mt][2] = x0.y; afh[mt][3] = x1.y;
                const uint32_t* q = Al + (wm + mt * 16 + g) * G_STRIDE + ks * 8 + 2 * t;
                uint2 y0 = *(const uint2*)q;
                uint2 y1 = *(const uint2*)(q + 8 * G_STRIDE);
                afl[mt][0] = y0.x; afl[mt][1] = y1.x; afl[mt][2] = y0.y; afl[mt][3] = y1.y;
            }
#pragma unroll
            for (int j = 0; j < 8; j++) {
                uint2 bh = *(const uint2*)(Bh + (wn + j * 8 + g) * G_STRIDE + ks * 8 + 2 * t);
                uint2 bl = *(const uint2*)(Bl + (wn + j * 8 + g) * G_STRIDE + ks * 8 + 2 * t);
#pragma unroll
                for (int mt = 0; mt < 2; mt++) {
                    mma_bf16(acc[mt][j], afh[mt], bh);
                    mma_bf16(acc[mt][j], afh[mt], bl);
                    mma_bf16(acc[mt][j], afl[mt], bh);
                }
            }
        }
    }

    // bias values for owned columns
    float bv2[8][2];
#pragma unroll
    for (int j = 0; j < 8; j++) {
        const int n = bn + wn + j * 8 + 2 * t;
        bv2[j][0] = bias[n];
        bv2[j][1] = bias[n + 1];
    }

    if (z < 2) {
        uint32_t* PH = (z == 0) ? g_Qh : g_Kh;
        uint32_t* PL = (z == 0) ? g_Ql : g_Kl;
        const float scale = (z == 0) ? 0.125f : 1.0f;
        const int bhh_base = (bn + wn) >> 6;  // head index of this warp's n-range
#pragma unroll
        for (int mt = 0; mt < 2; mt++)
#pragma unroll
            for (int half = 0; half < 2; half++) {
                const int m = bm + wm + mt * 16 + half * 8 + g;
                const int b = m >> 11;
                const int s = m & (SEQ - 1);
                const size_t base = ((size_t)(b * NHEAD + bhh_base) * SEQ + s) * DPAIRS;
#pragma unroll
                for (int j = 0; j < 8; j++) {
                    float v0 = (acc[mt][j][half * 2 + 0] + bv2[j][0]) * scale;
                    float v1 = (acc[mt][j][half * 2 + 1] + bv2[j][1]) * scale;
                    uint32_t hw, lw;
                    split_pair(v0, v1, hw, lw);
                    const int word = (j >> 1) * 8 + 2 * t + (j & 1);
                    PH[base + word] = hw;
                    PL[base + word] = lw;
                }
            }
    } else {
        // V: stage fp32 tile to smem, transpose, split, write (B,H,Dh,S-pairs).
        float* Ts = (float*)smw;
        __syncthreads();
#pragma unroll
        for (int mt = 0; mt < 2; mt++)
#pragma unroll
            for (int half = 0; half < 2; half++) {
                const int ml = wm + mt * 16 + half * 8 + g;
#pragma unroll
                for (int j = 0; j < 8; j++) {
                    const int nl = wn + j * 8 + 2 * t;
                    Ts[ml * TS_LD + nl]     = acc[mt][j][half * 2 + 0] + bv2[j][0];
                    Ts[ml * TS_LD + nl + 1] = acc[mt][j][half * 2 + 1] + bv2[j][1];
                }
            }
        __syncthreads();
        const int b = bm >> 11;
        const int sloc = bm & (SEQ - 1);      // sequence-local row base (batch removed)
#pragma unroll
        for (int i = 0; i < 32; i++) {
            const int linear = i * 256 + tid;     // 8192 pair-elements
            const int dloc = linear >> 6;         // 0..127
            const int sp = linear & 63;           // s-pair within tile
            const float v0 = Ts[(2 * sp) * TS_LD + dloc];
            const float v1 = Ts[(2 * sp + 1) * TS_LD + dloc];
            uint32_t hw, lw;
            split_pair(v0, v1, hw, lw);
            const int dg = bn + dloc;
            const int h = dg >> 6, dh = dg & 63;
            const int aps = (sloc >> 1) + sp;     // sequence-local s-pair index
            const int word = (aps & ~7) + permpos(sp & 7);
            const size_t addr = ((size_t)(b * NHEAD + h) * NHID + dh) * SPAIRS + word;
            g_VTh[addr] = hw;
            g_VTl[addr] = lw;
        }
    }
}

// ---------------------------------------------------------------------------
// Flash attention, bf16-split. BQ=256, BKV=64, 8 warps (32q x 64kv, mt=2).
// P never leaves registers (bf16 C-layout == A-layout). Row stride 40 words.
// ---------------------------------------------------------------------------
#define A_STRIDE 40
#define QW (256 * A_STRIDE)      /* 10240 words per Q plane */
#define KVW (64 * A_STRIDE)      /* 2560 words per KV plane per buffer */
#define ATT_SMEM_WORDS (2 * QW + 8 * KVW)   /* 40960 */
#define ATT_SMEM_BYTES (ATT_SMEM_WORDS * 4) /* 163840 */
#define O_QH 0
#define O_QL QW
#define O_KH (2 * QW)
#define O_KL (2 * QW + 2 * KVW)
#define O_VH (2 * QW + 4 * KVW)
#define O_VL (2 * QW + 6 * KVW)

__device__ __forceinline__ void attn_stage_kv(const uint32_t* Kh, const uint32_t* Kl,
                                              const uint32_t* Vh, const uint32_t* Vl,
                                              uint32_t smBase, int tid, int it) {
    const int buf = it & 1;
    const int kv0 = it * 64;
#pragma unroll
    for (int i = 0; i < 2; i++) {
        const int c = tid + 256 * i;        // 0..511 chunks (16B) per plane
        const int row = c >> 3;
        const int off = (c & 7) * 4;        // word offset
        const uint32_t d = smBase + (buf * KVW + row * A_STRIDE + off) * 4;
        cp_async16(d + O_KH * 4, Kh + (size_t)(kv0 + row) * DPAIRS + off);
        cp_async16(d + O_KL * 4, Kl + (size_t)(kv0 + row) * DPAIRS + off);
        cp_async16(d + O_VH * 4, Vh + (size_t)row * SPAIRS + it * DPAIRS + off);
        cp_async16(d + O_VL * 4, Vl + (size_t)row * SPAIRS + it * DPAIRS + off);
    }
    cp_commit();
}

__global__ __launch_bounds__(256, 1) void attn_bf16(float* __restrict__ out)
{
    extern __shared__ uint32_t smw[];

    const int tid = threadIdx.x;
    const int warp = tid >> 5, lane = tid & 31;
    const int g = lane >> 2, t = lane & 3;
    const int bh = blockIdx.y;
    const int q0 = blockIdx.x * 256;
    const int wq = warp * 32;

    const uint32_t* Qh = g_Qh + ((size_t)bh * SEQ + q0) * DPAIRS;
    const uint32_t* Ql = g_Ql + ((size_t)bh * SEQ + q0) * DPAIRS;
    const uint32_t* Kh = g_Kh + (size_t)bh * SEQ * DPAIRS;
    const uint32_t* Kl = g_Kl + (size_t)bh * SEQ * DPAIRS;
    const uint32_t* Vh = g_VTh + (size_t)bh * NHID * SPAIRS;
    const uint32_t* Vl = g_VTl + (size_t)bh * NHID * SPAIRS;

    const uint32_t smBase = (uint32_t)__cvta_generic_to_shared(smw);

    // Q tile: 256 rows x 32 words x 2 planes = 4096 16B chunks.
#pragma unroll
    for (int i = 0; i < 8; i++) {
        const int c = tid + 256 * i;   // chunk within one plane (0..2047)
        const int row = c >> 3;
        const int off = (c & 7) * 4;
        cp_async16(smBase + (O_QH + row * A_STRIDE + off) * 4, Qh + (size_t)row * DPAIRS + off);
        cp_async16(smBase + (O_QL + row * A_STRIDE + off) * 4, Ql + (size_t)row * DPAIRS + off);
    }
    attn_stage_kv(Kh, Kl, Vh, Vl, smBase, tid, 0);  // group 0 = Q + KV0
    attn_stage_kv(Kh, Kl, Vh, Vl, smBase, tid, 1);  // group 1

    float m_i[4], l_i[4], O[2][8][4];
#pragma unroll
    for (int r = 0; r < 4; r++) { m_i[r] = -INFINITY; l_i[r] = 0.0f; }
#pragma unroll
    for (int mt = 0; mt < 2; mt++)
#pragma unroll
        for (int j = 0; j < 8; j++)
#pragma unroll
            for (int c = 0; c < 4; c++) O[mt][j][c] = 0.0f;

    const int NIT = SEQ / 64;  // 32
    for (int it = 0; it < NIT; it++) {
        if (it == NIT - 1) cp_wait<0>(); else cp_wait<1>();
        __syncthreads();
        const int buf = it & 1;
        const uint32_t* KHb = smw + O_KH + buf * KVW;
        const uint32_t* KLb = smw + O_KL + buf * KVW;
        const uint32_t* VHb = smw + O_VH + buf * KVW;
        const uint32_t* VLb = smw + O_VL + buf * KVW;

        // ---- S = Q K^T, 3-term bf16 split ----
        float S[2][8][4];
#pragma unroll
        for (int mt = 0; mt < 2; mt++)
#pragma unroll
            for (int j = 0; j < 8; j++)
#pragma unroll
                for (int c = 0; c < 4; c++) S[mt][j][c] = 0.0f;

#pragma unroll
        for (int ks = 0; ks < 4; ks++) {
            uint32_t ah[2][4], al[2][4];
#pragma unroll
            for (int mt = 0; mt < 2; mt++) {
                const uint32_t* p = smw + O_QH + (wq + mt * 16 + g) * A_STRIDE + ks * 8 + 2 * t;
                uint2 x0 = *(const uint2*)p;
                uint2 x1 = *(const uint2*)(p + 8 * A_STRIDE);
                ah[mt][0] = x0.x; ah[mt][1] = x1.x; ah[mt][2] = x0.y; ah[mt][3] = x1.y;
                const uint32_t* q = smw + O_QL + (wq + mt * 16 + g) * A_STRIDE + ks * 8 + 2 * t;
                uint2 y0 = *(const uint2*)q;
                uint2 y1 = *(const uint2*)(q + 8 * A_STRIDE);
                al[mt][0] = y0.x; al[mt][1] = y1.x; al[mt][2] = y0.y; al[mt][3] = y1.y;
            }
#pragma unroll
            for (int j = 0; j < 8; j++) {
                uint2 bhf = *(const uint2*)(KHb + (j * 8 + g) * A_STRIDE + ks * 8 + 2 * t);
                uint2 blf = *(const uint2*)(KLb + (j * 8 + g) * A_STRIDE + ks * 8 + 2 * t);
#pragma unroll
                for (int mt = 0; mt < 2; mt++) {
                    mma_bf16(S[mt][j], ah[mt], bhf);
                    mma_bf16(S[mt][j], ah[mt], blf);
                    mma_bf16(S[mt][j], al[mt], bhf);
                }
            }
        }

        // ---- online softmax (rows per quad; shfl over t) ----
#pragma unroll
        for (int mt = 0; mt < 2; mt++) {
#pragma unroll
            for (int half = 0; half < 2; half++) {
                const int ri = mt * 2 + half;
                float mx = -INFINITY;
#pragma unroll
                for (int j = 0; j < 8; j++)
                    mx = fmaxf(mx, fmaxf(S[mt][j][half * 2], S[mt][j][half * 2 + 1]));
                mx = fmaxf(mx, __shfl_xor_sync(0xffffffffu, mx, 1));
                mx = fmaxf(mx, __shfl_xor_sync(0xffffffffu, mx, 2));
                const float mn = fmaxf(m_i[ri], mx);
                const float corr = __expf(m_i[ri] - mn);
                m_i[ri] = mn;
                float rs = 0.0f;
#pragma unroll
                for (int j = 0; j < 8; j++) {
                    const float e0 = __expf(S[mt][j][half * 2]     - mn);
                    const float e1 = __expf(S[mt][j][half * 2 + 1] - mn);
                    S[mt][j][half * 2]     = e0;
                    S[mt][j][half * 2 + 1] = e1;
                    rs += e0 + e1;
                }
                rs += __shfl_xor_sync(0xffffffffu, rs, 1);
                rs += __shfl_xor_sync(0xffffffffu, rs, 2);
                l_i[ri] = l_i[ri] * corr + rs;
#pragma unroll
                for (int j = 0; j < 8; j++) {
                    O[mt][j][half * 2]     *= corr;
                    O[mt][j][half * 2 + 1] *= corr;
                }
            }
        }

        // ---- O += P V : P assembled from S registers (C-layout == A-layout) ----
#pragma unroll
        for (int ks = 0; ks < 4; ks++) {
            uint32_t ph[2][4], pl[2][4];
#pragma unroll
            for (int mt = 0; mt < 2; mt++) {
                split_pair(S[mt][2 * ks][0],     S[mt][2 * ks][1],     ph[mt][0], pl[mt][0]);
                split_pair(S[mt][2 * ks][2],     S[mt][2 * ks][3],     ph[mt][1], pl[mt][1]);
                split_pair(S[mt][2 * ks + 1][0], S[mt][2 * ks + 1][1], ph[mt][2], pl[mt][2]);
                split_pair(S[mt][2 * ks + 1][2], S[mt][2 * ks + 1][3], ph[mt][3], pl[mt][3]);
            }
#pragma unroll
            for (int j = 0; j < 8; j++) {
                uint2 vh = *(const uint2*)(VHb + (j * 8 + g) * A_STRIDE + ks * 8 + 2 * t);
                uint2 vl = *(const uint2*)(VLb + (j * 8 + g) * A_STRIDE + ks * 8 + 2 * t);
#pragma unroll
                for (int mt = 0; mt < 2; mt++) {
                    mma_bf16(O[mt][j], ph[mt], vh);
                    mma_bf16(O[mt][j], ph[mt], vl);
                    mma_bf16(O[mt][j], pl[mt], vh);
                }
            }
        }

        __syncthreads();
        if (it + 2 < NIT) attn_stage_kv(Kh, Kl, Vh, Vl, smBase, tid, it + 2);
    }

    // Epilogue: normalize, write (B, S, H*Dh).
    const int b = bh >> 4, h = bh & 15;
#pragma unroll
    for (int mt = 0; mt < 2; mt++)
#pragma unroll
        for (int half = 0; half < 2; half++) {
            const int ri = mt * 2 + half;
            const float inv = 1.0f / l_i[ri];
            const int q = q0 + wq + mt * 16 + half * 8 + g;
            float* orow = out + (size_t)(b * SEQ + q) * NTOT + h * NHID;
#pragma unroll
            for (int j = 0; j < 8; j++) {
                float2 v = make_float2(O[mt][j][half * 2] * inv,
                                       O[mt][j][half * 2 + 1] * inv);
                *(float2*)(orow + j * 8 + 2 * t) = v;
            }
        }
}

// ---------------------------------------------------------------------------
extern "C" void kernel_launch(void* const* d_in, const int* in_sizes, int n_in,
                              void* d_out, int out_size)
{
    const float* xq = (const float*)d_in[0];
    const float* xk = (const float*)d_in[1];
    const float* xv = (const float*)d_in[2];
    const float* wq = (const float*)d_in[3];
    const float* bq = (const float*)d_in[4];
    const float* wk = (const float*)d_in[5];
    const float* bk = (const float*)d_in[6];
    const float* wv = (const float*)d_in[7];
    const float* bv = (const float*)d_in[8];
    float* out = (float*)d_out;

    cudaFuncSetAttribute(qkv_gemm_bf16, cudaFuncAttributeMaxDynamicSharedMemorySize,
                         GEMM_SMEM_BYTES);
    cudaFuncSetAttribute(attn_bf16, cudaFuncAttributeMaxDynamicSharedMemorySize,
                         ATT_SMEM_BYTES);

    dim3 gg(NTOT / 128, MTOT / 128, 3);
    qkv_gemm_bf16<<<gg, 256, GEMM_SMEM_BYTES>>>(xq, xk, xv, wq, bq, wk, bk, wv, bv);

    dim3 ga(SEQ / 256, BH);
    attn_bf16<<<ga, 256, ATT_SMEM_BYTES>>>(out);
}

// round 7
// speedup vs baseline: 1.5442x; 1.5442x over previous
#include <cuda_runtime.h>
#include <cuda_fp16.h>
#include <math.h>
#include <stdint.h>

#define D_IN 1024
#define NHEAD 16
#define NHID 64
#define BATCH 2
#define SEQ 2048
#define MTOT (BATCH * SEQ)   /* 4096 */
#define NTOT (NHEAD * NHID)  /* 1024 */
#define BH (BATCH * NHEAD)   /* 32 */
#define DPAIRS (NHID / 2)    /* 32 */
#define SPAIRS (SEQ / 2)     /* 1024 */
#define XW 512               /* pair-words per row of X/W planes */

// fp16 pair-packed planes, k-pairs permuted [p0,p4,p1,p5,p2,p6,p3,p7] per 8-group.
__device__ uint32_t g_Xh[(size_t)3 * MTOT * XW];
__device__ uint32_t g_Xl[(size_t)3 * MTOT * XW];
__device__ uint32_t g_Wh[(size_t)3 * NTOT * XW];
__device__ uint32_t g_Wl[(size_t)3 * NTOT * XW];
// Q/K: (B,H,S,Dh-pairs) split planes (Q pre-scaled by 0.125). V: (B,H,Dh,S-pairs) hi only.
__device__ uint32_t g_Qh[(size_t)BH * SEQ * DPAIRS];
__device__ uint32_t g_Ql[(size_t)BH * SEQ * DPAIRS];
__device__ uint32_t g_Kh[(size_t)BH * SEQ * DPAIRS];
__device__ uint32_t g_Kl[(size_t)BH * SEQ * DPAIRS];
__device__ uint32_t g_VTh[(size_t)BH * NHID * SPAIRS];

// ---------------------------------------------------------------------------
__device__ __forceinline__ int permpos(int p) { return p < 4 ? 2 * p : 2 * p - 7; }

__device__ __forceinline__ uint32_t f2h2(float a, float b) {
    __half2 h = __float22half2_rn(make_float2(a, b));
    return *reinterpret_cast<uint32_t*>(&h);
}
__device__ __forceinline__ void split_h(float a, float b, uint32_t& h, uint32_t& l) {
    __half2 H = __float22half2_rn(make_float2(a, b));
    float2 Hf = __half22float2(H);
    __half2 L = __float22half2_rn(make_float2(a - Hf.x, b - Hf.y));
    h = *reinterpret_cast<uint32_t*>(&H);
    l = *reinterpret_cast<uint32_t*>(&L);
}
__device__ __forceinline__ void mma_fp16(float* d, const uint32_t* a, uint2 b) {
    asm volatile(
        "mma.sync.aligned.m16n8k16.row.col.f32.f16.f16.f32 "
        "{%0,%1,%2,%3}, {%4,%5,%6,%7}, {%8,%9}, {%0,%1,%2,%3};\n"
        : "+f"(d[0]), "+f"(d[1]), "+f"(d[2]), "+f"(d[3])
        : "r"(a[0]), "r"(a[1]), "r"(a[2]), "r"(a[3]), "r"(b.x), "r"(b.y));
}
__device__ __forceinline__ void cp_async16(uint32_t dst, const void* src) {
    asm volatile("cp.async.cg.shared.global [%0], [%1], 16;\n" :: "r"(dst), "l"(src));
}
__device__ __forceinline__ void cp_commit() { asm volatile("cp.async.commit_group;\n"); }
template <int N>
__device__ __forceinline__ void cp_wait() { asm volatile("cp.async.wait_group %0;\n" :: "n"(N)); }

// ---------------------------------------------------------------------------
// Prep: split X (hi+lo) and W (hi+lo) into fp16 pair planes, permuted.
// ---------------------------------------------------------------------------
#define XTOT (3 * MTOT * XW)  /* 6291456 */
#define WTOT (3 * NTOT * XW)  /* 1572864 */
#define PREP_BLOCKS ((XTOT + WTOT) / 256)  /* 30720 */

__global__ __launch_bounds__(256) void prep_split(
    const float* __restrict__ xq, const float* __restrict__ xk, const float* __restrict__ xv,
    const float* __restrict__ wq, const float* __restrict__ wk, const float* __restrict__ wv)
{
    const int idx = blockIdx.x * 256 + threadIdx.x;
    if (idx < XTOT) {
        const int z = idx / (MTOT * XW);
        const int r = idx - z * (MTOT * XW);
        const int row = r >> 9, p = r & (XW - 1);
        const float* X = (z == 0) ? xq : (z == 1) ? xk : xv;
        float2 v = *(const float2*)(X + (size_t)row * D_IN + 2 * p);
        uint32_t h, l;
        split_h(v.x, v.y, h, l);
        const int word = (p & ~7) + permpos(p & 7);
        g_Xh[(size_t)z * MTOT * XW + (size_t)row * XW + word] = h;
        g_Xl[(size_t)z * MTOT * XW + (size_t)row * XW + word] = l;
    } else {
        const int r2 = idx - XTOT;
        const int z = r2 / (NTOT * XW);
        const int r = r2 - z * (NTOT * XW);
        const int row = r >> 9, p = r & (XW - 1);
        const float* W = (z == 0) ? wq : (z == 1) ? wk : wv;
        float2 v = *(const float2*)(W + (size_t)row * D_IN + 2 * p);
        uint32_t h, l;
        split_h(v.x, v.y, h, l);
        const int word = (p & ~7) + permpos(p & 7);
        g_Wh[(size_t)z * NTOT * XW + (size_t)row * XW + word] = h;
        g_Wl[(size_t)z * NTOT * XW + (size_t)row * XW + word] = l;
    }
}

// ---------------------------------------------------------------------------
// Fused QKV GEMM, fp16 3-term (AhBh + AlBh + AhBl). Block 128x128, ktile 32,
// 8 warps (32m x 64n), cp.async double-buffered pre-split planes.
// Plane row stride 24 words (16 data + 8 pad; 24 mod 32 = 24 -> LDS.64 clean).
// ---------------------------------------------------------------------------
#define G_STRIDE 24
#define G_TILE (128 * G_STRIDE)            /* 3072 words */
#define GEMM_SMEM_WORDS (4 * 2 * G_TILE)   /* 24576 */
#define GEMM_SMEM_BYTES (GEMM_SMEM_WORDS * 4)  /* 98304 */
#define TS_LD 130

__global__ __launch_bounds__(256, 2) void qkv_gemm_fp16(
    const float* __restrict__ bq, const float* __restrict__ bk, const float* __restrict__ bv)
{
    extern __shared__ uint32_t smw[];
    const int z = blockIdx.z;
    const float* bias = (z == 0) ? bq : (z == 1) ? bk : bv;

    const int tid = threadIdx.x;
    const int bm = blockIdx.y * 128;
    const int bn = blockIdx.x * 128;
    const int warp = tid >> 5, lane = tid & 31;
    const int g = lane >> 2, t = lane & 3;
    const int wm = (warp >> 1) * 32;
    const int wn = (warp & 1) * 64;

    const uint32_t smBase = (uint32_t)__cvta_generic_to_shared(smw);
    const int r0 = tid >> 2;             // 0..63
    const int woff = (tid & 3) * 4;

    const uint32_t* srcBase[4];
    srcBase[0] = g_Xh + (size_t)z * MTOT * XW + (size_t)bm * XW;
    srcBase[1] = g_Xl + (size_t)z * MTOT * XW + (size_t)bm * XW;
    srcBase[2] = g_Wh + (size_t)z * NTOT * XW + (size_t)bn * XW;
    srcBase[3] = g_Wl + (size_t)z * NTOT * XW + (size_t)bn * XW;

#define GEMM_ISSUE(KT) do {                                                     \
    const int _buf = (KT) & 1;                                                  \
    _Pragma("unroll")                                                           \
    for (int _i = 0; _i < 8; _i++) {                                            \
        const int _pl = _i >> 1;                                                \
        const int _row = ((_i & 1) << 6) + r0;                                  \
        cp_async16(smBase + (_pl * 2 * G_TILE + _buf * G_TILE +                 \
                             _row * G_STRIDE + woff) * 4,                       \
                   srcBase[_pl] + (size_t)_row * XW + (KT) * 16 + woff);        \
    }                                                                           \
    cp_commit();                                                                \
} while (0)

    float acc[2][8][4];
#pragma unroll
    for (int mt = 0; mt < 2; mt++)
#pragma unroll
        for (int j = 0; j < 8; j++)
#pragma unroll
            for (int c = 0; c < 4; c++) acc[mt][j][c] = 0.0f;

    GEMM_ISSUE(0);
    GEMM_ISSUE(1);

    const int NKT = D_IN / 32;  // 32
    for (int kt = 0; kt < NKT; kt++) {
        if (kt == NKT - 1) cp_wait<0>(); else cp_wait<1>();
        __syncthreads();
        const int buf = kt & 1;
        const uint32_t* Ahb = smw + 0 * 2 * G_TILE + buf * G_TILE;
        const uint32_t* Alb = smw + 1 * 2 * G_TILE + buf * G_TILE;
        const uint32_t* Bhb = smw + 2 * 2 * G_TILE + buf * G_TILE;
        const uint32_t* Blb = smw + 3 * 2 * G_TILE + buf * G_TILE;
#pragma unroll
        for (int ks = 0; ks < 2; ks++) {
            uint32_t ah[2][4], al[2][4];
#pragma unroll
            for (int mt = 0; mt < 2; mt++) {
                const uint32_t* p = Ahb + (wm + mt * 16 + g) * G_STRIDE + ks * 8 + 2 * t;
                uint2 x0 = *(const uint2*)p;
                uint2 x1 = *(const uint2*)(p + 8 * G_STRIDE);
                ah[mt][0] = x0.x; ah[mt][1] = x1.x; ah[mt][2] = x0.y; ah[mt][3] = x1.y;
                const uint32_t* q = Alb + (wm + mt * 16 + g) * G_STRIDE + ks * 8 + 2 * t;
                uint2 y0 = *(const uint2*)q;
                uint2 y1 = *(const uint2*)(q + 8 * G_STRIDE);
                al[mt][0] = y0.x; al[mt][1] = y1.x; al[mt][2] = y0.y; al[mt][3] = y1.y;
            }
#pragma unroll
            for (int j = 0; j < 8; j++) {
                uint2 bh = *(const uint2*)(Bhb + (wn + j * 8 + g) * G_STRIDE + ks * 8 + 2 * t);
                uint2 bl = *(const uint2*)(Blb + (wn + j * 8 + g) * G_STRIDE + ks * 8 + 2 * t);
#pragma unroll
                for (int mt = 0; mt < 2; mt++) {
                    mma_fp16(acc[mt][j], ah[mt], bh);
                    mma_fp16(acc[mt][j], al[mt], bh);
                    mma_fp16(acc[mt][j], ah[mt], bl);
                }
            }
        }
        __syncthreads();
        if (kt + 2 < NKT) GEMM_ISSUE(kt + 2);
    }

    float bv2[8][2];
#pragma unroll
    for (int j = 0; j < 8; j++) {
        const int n = bn + wn + j * 8 + 2 * t;
        bv2[j][0] = bias[n];
        bv2[j][1] = bias[n + 1];
    }

    if (z < 2) {
        uint32_t* PH = (z == 0) ? g_Qh : g_Kh;
        uint32_t* PL = (z == 0) ? g_Ql : g_Kl;
        const float scale = (z == 0) ? 0.125f : 1.0f;
        const int head = (bn + wn) >> 6;
#pragma unroll
        for (int mt = 0; mt < 2; mt++)
#pragma unroll
            for (int half = 0; half < 2; half++) {
                const int m = bm + wm + mt * 16 + half * 8 + g;
                const int b = m >> 11;
                const int s = m & (SEQ - 1);
                const size_t base = ((size_t)(b * NHEAD + head) * SEQ + s) * DPAIRS;
#pragma unroll
                for (int j = 0; j < 8; j++) {
                    float v0 = (acc[mt][j][half * 2 + 0] + bv2[j][0]) * scale;
                    float v1 = (acc[mt][j][half * 2 + 1] + bv2[j][1]) * scale;
                    uint32_t hw, lw;
                    split_h(v0, v1, hw, lw);
                    const int word = (j >> 1) * 8 + 2 * t + (j & 1);
                    PH[base + word] = hw;
                    PL[base + word] = lw;
                }
            }
    } else {
        // V: fp32 transpose through smem, store hi plane only, (B,H,Dh,S-pairs).
        float* Ts = (float*)smw;
        __syncthreads();
#pragma unroll
        for (int mt = 0; mt < 2; mt++)
#pragma unroll
            for (int half = 0; half < 2; half++) {
                const int ml = wm + mt * 16 + half * 8 + g;
#pragma unroll
                for (int j = 0; j < 8; j++) {
                    const int nl = wn + j * 8 + 2 * t;
                    Ts[ml * TS_LD + nl]     = acc[mt][j][half * 2 + 0] + bv2[j][0];
                    Ts[ml * TS_LD + nl + 1] = acc[mt][j][half * 2 + 1] + bv2[j][1];
                }
            }
        __syncthreads();
        const int b = bm >> 11;
        const int sloc = bm & (SEQ - 1);
#pragma unroll
        for (int i = 0; i < 32; i++) {
            const int linear = i * 256 + tid;
            const int dloc = linear >> 6;
            const int sp = linear & 63;
            const float v0 = Ts[(2 * sp) * TS_LD + dloc];
            const float v1 = Ts[(2 * sp + 1) * TS_LD + dloc];
            const int dg = bn + dloc;
            const int h = dg >> 6, dh = dg & 63;
            const int aps = (sloc >> 1) + sp;
            const int word = (aps & ~7) + permpos(sp & 7);
            g_VTh[((size_t)(b * NHEAD + h) * NHID + dh) * SPAIRS + word] = f2h2(v0, v1);
        }
    }
#undef GEMM_ISSUE
}

// ---------------------------------------------------------------------------
// Flash attention, fp16. BQ=128, BKV=64, 8 warps (16q x 64kv), 2 CTAs/SM.
// QK 3-term (QhKh + QlKh + QhKl); PV 1-term (P fp16 single x Vh single).
// Row stride 40 words (40 mod 32 = 8 -> conflict-free LDS.64).
// ---------------------------------------------------------------------------
#define A_STRIDE 40
#define QW (128 * A_STRIDE)      /* 5120 words per Q plane */
#define KVW (64 * A_STRIDE)      /* 2560 words per KV plane per buffer */
#define O_QH 0
#define O_QL QW
#define O_KH (2 * QW)                 /* 10240 */
#define O_KL (2 * QW + 2 * KVW)       /* 15360 */
#define O_VH (2 * QW + 4 * KVW)       /* 20480 */
#define ATT_SMEM_WORDS (2 * QW + 6 * KVW)   /* 25600 */
#define ATT_SMEM_BYTES (ATT_SMEM_WORDS * 4) /* 102400 */

__device__ __forceinline__ void attn_stage_kv(const uint32_t* Kh, const uint32_t* Kl,
                                              const uint32_t* Vh,
                                              uint32_t smBase, int tid, int it) {
    const int buf = it & 1;
    const int kv0 = it * 64;
#pragma unroll
    for (int i = 0; i < 2; i++) {
        const int row = i * 32 + (tid >> 3);       // 0..63
        const int off = (tid & 7) * 4;             // word offset in 32-word row
        const uint32_t d = smBase + (buf * KVW + row * A_STRIDE + off) * 4;
        cp_async16(d + O_KH * 4, Kh + (size_t)(kv0 + row) * DPAIRS + off);
        cp_async16(d + O_KL * 4, Kl + (size_t)(kv0 + row) * DPAIRS + off);
        cp_async16(d + O_VH * 4, Vh + (size_t)row * SPAIRS + it * DPAIRS + off);
    }
    cp_commit();
}

__global__ __launch_bounds__(256, 2) void attn_fp16(float* __restrict__ out)
{
    extern __shared__ uint32_t smw[];

    const int tid = threadIdx.x;
    const int warp = tid >> 5, lane = tid & 31;
    const int g = lane >> 2, t = lane & 3;
    const int bh = blockIdx.y;
    const int q0 = blockIdx.x * 128;
    const int wq = warp * 16;

    const uint32_t* Qh = g_Qh + ((size_t)bh * SEQ + q0) * DPAIRS;
    const uint32_t* Ql = g_Ql + ((size_t)bh * SEQ + q0) * DPAIRS;
    const uint32_t* Kh = g_Kh + (size_t)bh * SEQ * DPAIRS;
    const uint32_t* Kl = g_Kl + (size_t)bh * SEQ * DPAIRS;
    const uint32_t* Vh = g_VTh + (size_t)bh * NHID * SPAIRS;

    const uint32_t smBase = (uint32_t)__cvta_generic_to_shared(smw);

    // Q tile: 128 rows x 32 words x 2 planes = 2048 16B chunks.
#pragma unroll
    for (int i = 0; i < 4; i++) {
        const int c = tid + 256 * i;   // 0..1023 per plane
        const int row = c >> 3;
        const int off = (c & 7) * 4;
        cp_async16(smBase + (O_QH + row * A_STRIDE + off) * 4, Qh + (size_t)row * DPAIRS + off);
        cp_async16(smBase + (O_QL + row * A_STRIDE + off) * 4, Ql + (size_t)row * DPAIRS + off);
    }
    attn_stage_kv(Kh, Kl, Vh, smBase, tid, 0);   // group 0 = Q + KV0
    attn_stage_kv(Kh, Kl, Vh, smBase, tid, 1);   // group 1

    float m_i[2], l_i[2], O[8][4];
#pragma unroll
    for (int r = 0; r < 2; r++) { m_i[r] = -INFINITY; l_i[r] = 0.0f; }
#pragma unroll
    for (int j = 0; j < 8; j++)
#pragma unroll
        for (int c = 0; c < 4; c++) O[j][c] = 0.0f;

    const int NIT = SEQ / 64;  // 32
    for (int it = 0; it < NIT; it++) {
        if (it == NIT - 1) cp_wait<0>(); else cp_wait<1>();
        __syncthreads();
        const int buf = it & 1;
        const uint32_t* Khb = smw + O_KH + buf * KVW;
        const uint32_t* Klb = smw + O_KL + buf * KVW;
        const uint32_t* Vhb = smw + O_VH + buf * KVW;

        // ---- S = Q K^T (3-term) ----
        float S[8][4];
#pragma unroll
        for (int j = 0; j < 8; j++)
#pragma unroll
            for (int c = 0; c < 4; c++) S[j][c] = 0.0f;

#pragma unroll
        for (int ks = 0; ks < 4; ks++) {
            uint32_t qh[4], ql[4];
            {
                const uint32_t* p = smw + O_QH + (wq + g) * A_STRIDE + ks * 8 + 2 * t;
                uint2 x0 = *(const uint2*)p;
                uint2 x1 = *(const uint2*)(p + 8 * A_STRIDE);
                qh[0] = x0.x; qh[1] = x1.x; qh[2] = x0.y; qh[3] = x1.y;
                const uint32_t* q = smw + O_QL + (wq + g) * A_STRIDE + ks * 8 + 2 * t;
                uint2 y0 = *(const uint2*)q;
                uint2 y1 = *(const uint2*)(q + 8 * A_STRIDE);
                ql[0] = y0.x; ql[1] = y1.x; ql[2] = y0.y; ql[3] = y1.y;
            }
#pragma unroll
            for (int j = 0; j < 8; j++) {
                uint2 kh = *(const uint2*)(Khb + (j * 8 + g) * A_STRIDE + ks * 8 + 2 * t);
                uint2 kl = *(const uint2*)(Klb + (j * 8 + g) * A_STRIDE + ks * 8 + 2 * t);
                mma_fp16(S[j], qh, kh);
                mma_fp16(S[j], ql, kh);
                mma_fp16(S[j], qh, kl);
            }
        }

        // ---- online softmax (2 rows per thread; shfl over t) ----
#pragma unroll
        for (int half = 0; half < 2; half++) {
            float mx = -INFINITY;
#pragma unroll
            for (int j = 0; j < 8; j++)
                mx = fmaxf(mx, fmaxf(S[j][half * 2], S[j][half * 2 + 1]));
            mx = fmaxf(mx, __shfl_xor_sync(0xffffffffu, mx, 1));
            mx = fmaxf(mx, __shfl_xor_sync(0xffffffffu, mx, 2));
            const float mn = fmaxf(m_i[half], mx);
            const float corr = __expf(m_i[half] - mn);
            m_i[half] = mn;
            float rs = 0.0f;
#pragma unroll
            for (int j = 0; j < 8; j++) {
                const float e0 = __expf(S[j][half * 2]     - mn);
                const float e1 = __expf(S[j][half * 2 + 1] - mn);
                S[j][half * 2]     = e0;
                S[j][half * 2 + 1] = e1;
                rs += e0 + e1;
            }
            rs += __shfl_xor_sync(0xffffffffu, rs, 1);
            rs += __shfl_xor_sync(0xffffffffu, rs, 2);
            l_i[half] = l_i[half] * corr + rs;
#pragma unroll
            for (int j = 0; j < 8; j++) {
                O[j][half * 2]     *= corr;
                O[j][half * 2 + 1] *= corr;
            }
        }

        // ---- O += P V (P single fp16 from S regs; V hi plane) ----
#pragma unroll
        for (int ks = 0; ks < 4; ks++) {
            uint32_t pf[4];
            pf[0] = f2h2(S[2 * ks][0],     S[2 * ks][1]);
            pf[1] = f2h2(S[2 * ks][2],     S[2 * ks][3]);
            pf[2] = f2h2(S[2 * ks + 1][0], S[2 * ks + 1][1]);
            pf[3] = f2h2(S[2 * ks + 1][2], S[2 * ks + 1][3]);
#pragma unroll
            for (int j = 0; j < 8; j++) {
                uint2 vh = *(const uint2*)(Vhb + (j * 8 + g) * A_STRIDE + ks * 8 + 2 * t);
                mma_fp16(O[j], pf, vh);
            }
        }

        __syncthreads();
        if (it + 2 < NIT) attn_stage_kv(Kh, Kl, Vh, smBase, tid, it + 2);
    }

    // Epilogue: normalize, write (B, S, H*Dh).
    const int b = bh >> 4, h = bh & 15;
#pragma unroll
    for (int half = 0; half < 2; half++) {
        const float inv = 1.0f / l_i[half];
        const int q = q0 + wq + half * 8 + g;
        float* orow = out + (size_t)(b * SEQ + q) * NTOT + h * NHID;
#pragma unroll
        for (int j = 0; j < 8; j++) {
            float2 v = make_float2(O[j][half * 2] * inv, O[j][half * 2 + 1] * inv);
            *(float2*)(orow + j * 8 + 2 * t) = v;
        }
    }
}

// ---------------------------------------------------------------------------
extern "C" void kernel_launch(void* const* d_in, const int* in_sizes, int n_in,
                              void* d_out, int out_size)
{
    const float* xq = (const float*)d_in[0];
    const float* xk = (const float*)d_in[1];
    const float* xv = (const float*)d_in[2];
    const float* wq = (const float*)d_in[3];
    const float* bq = (const float*)d_in[4];
    const float* wk = (const float*)d_in[5];
    const float* bk = (const float*)d_in[6];
    const float* wv = (const float*)d_in[7];
    const float* bv = (const float*)d_in[8];
    float* out = (float*)d_out;

    cudaFuncSetAttribute(qkv_gemm_fp16, cudaFuncAttributeMaxDynamicSharedMemorySize,
                         GEMM_SMEM_BYTES);
    cudaFuncSetAttribute(attn_fp16, cudaFuncAttributeMaxDynamicSharedMemorySize,
                         ATT_SMEM_BYTES);

    prep_split<<<PREP_BLOCKS, 256>>>(xq, xk, xv, wq, wk, wv);

    dim3 gg(NTOT / 128, MTOT / 128, 3);
    qkv_gemm_fp16<<<gg, 256, GEMM_SMEM_BYTES>>>(bq, bk, bv);

    dim3 ga(SEQ / 128, BH);
    attn_fp16<<<ga, 256, ATT_SMEM_BYTES>>>(out);
}